// round 13
// baseline (speedup 1.0000x reference)
#include <cuda_runtime.h>
#include <math.h>
#include <stdint.h>

// ---------------- problem constants ----------------
#define BATCH   2
#define LTXT    256
#define NIMG    2048
#define NTOK    2304          // LTXT + NIMG
#define DMODEL  1536
#define NH      12
#define DHEAD   128
#define TD      4608          // 3*DMODEL
#define MLPH    6144
#define ROWS    (BATCH*NTOK)  // 4608

// ---------------- device scratch (no allocs allowed) ----------------
__device__ __align__(128) float g_x   [ROWS*DMODEL];
__device__ __align__(128) float g_xn  [ROWS*DMODEL];
__device__ __align__(128) float g_q   [ROWS*DMODEL];
__device__ __align__(128) float g_k   [ROWS*DMODEL];
__device__ __align__(128) float g_v   [ROWS*DMODEL];
__device__ __align__(128) float g_attn[ROWS*DMODEL];
__device__ __align__(128) float g_h   [ROWS*MLPH];
__device__ __align__(128) float g_mod [BATCH*TD];

// ---------------- helpers ----------------
__device__ __forceinline__ float blockReduceSum256(float v, float* red) {
    int tid = threadIdx.x;
    red[tid] = v;
    __syncthreads();
    #pragma unroll
    for (int s = 128; s > 0; s >>= 1) {
        if (tid < s) red[tid] += red[tid + s];
        __syncthreads();
    }
    return red[0];
}

__device__ __forceinline__ float gelu_tanh(float x) {
    float x3 = x * x * x;
    return 0.5f * x * (1.f + tanhf(0.7978845608028654f * (x + 0.044715f * x3)));
}

__device__ __forceinline__ float to_tf32(float x) {
    unsigned u;
    asm("cvt.rna.tf32.f32 %0, %1;" : "=r"(u) : "f"(x));
    return __uint_as_float(u);
}

__device__ __forceinline__ void mma_tf32(float c[4], float a0, float a1, float a2, float a3,
                                         float b0, float b1) {
    asm volatile(
        "mma.sync.aligned.m16n8k8.row.col.f32.tf32.tf32.f32 "
        "{%0,%1,%2,%3}, {%4,%5,%6,%7}, {%8,%9}, {%0,%1,%2,%3};"
        : "+f"(c[0]), "+f"(c[1]), "+f"(c[2]), "+f"(c[3])
        : "r"(__float_as_uint(a0)), "r"(__float_as_uint(a1)),
          "r"(__float_as_uint(a2)), "r"(__float_as_uint(a3)),
          "r"(__float_as_uint(b0)), "r"(__float_as_uint(b1)));
}

__device__ __forceinline__ void cp16(uint32_t dst, const void* src) {
    asm volatile("cp.async.cg.shared.global [%0], [%1], 16;\n" :: "r"(dst), "l"(src));
}
__device__ __forceinline__ void cp_commit() {
    asm volatile("cp.async.commit_group;\n" ::: "memory");
}
__device__ __forceinline__ void cp_wait1() {
    asm volatile("cp.async.wait_group 1;\n" ::: "memory");
}

// ---------------- K1: modulation  emb = silu(vec) @ w_mod^T + b_mod ----------------
__global__ void __launch_bounds__(256) mod_kernel(
    const float* __restrict__ vec, const float* __restrict__ wmod,
    const float* __restrict__ bmod)
{
    __shared__ float red[256];
    int o = blockIdx.x;
    int b = o / TD;
    int j = o - b * TD;
    const float* v = vec + b * DMODEL;
    const float* w = wmod + (size_t)j * DMODEL;
    float s = 0.f;
    for (int i = threadIdx.x; i < DMODEL; i += 256) {
        float x = v[i];
        s += (x / (1.f + __expf(-x))) * w[i];
    }
    s = blockReduceSum256(s, red);
    if (threadIdx.x == 0) g_mod[o] = s + bmod[j];
}

// ---------------- K2: concat + RMSNorm (+ optional AdaLN modulate) ----------------
template<bool MOD1>
__global__ void __launch_bounds__(256) norm_kernel(
    const float* __restrict__ txt, const float* __restrict__ img,
    const float* __restrict__ w)
{
    __shared__ float red[256];
    int r = blockIdx.x;
    int b = r / NTOK;
    int n = r - b * NTOK;
    float* xrow = g_x + (size_t)r * DMODEL;
    const float* src;
    if (MOD1) {
        src = (n < LTXT) ? txt + (size_t)(b * LTXT + n) * DMODEL
                         : img + (size_t)(b * NIMG + n - LTXT) * DMODEL;
    } else {
        src = xrow;
    }
    float ss = 0.f;
    for (int i = threadIdx.x; i < DMODEL; i += 256) {
        float v = src[i];
        if (MOD1) xrow[i] = v;
        ss += v * v;
    }
    ss = blockReduceSum256(ss, red);
    float inv = rsqrtf(ss * (1.f / DMODEL) + 1e-6f);
    float* dst = g_xn + (size_t)r * DMODEL;
    if (MOD1) {
        const float* shift = g_mod + b * TD;
        const float* scale = shift + DMODEL;
        for (int i = threadIdx.x; i < DMODEL; i += 256)
            dst[i] = xrow[i] * inv * w[i] * (1.f + scale[i]) + shift[i];
    } else {
        for (int i = threadIdx.x; i < DMODEL; i += 256)
            dst[i] = src[i] * inv * w[i];
    }
}

// ---------------- K3: tf32 GEMM, 2-stage cp.async double buffer ----------------
// C = A(M,K) @ Bw(Nc,K)^T + epilogue.  Block 128x128, K-tile 16, 8 warps (2x4),
// warp tile 64x32, mma m16n8k8.  Fragments rna-rounded to tf32 after LDS.
// EPI 1: gelu(acc+bias)  (fc1)
// EPI 2: res + gate*acc  (out-proj, in-place g_x)
// EPI 3: acc+bias+res, scatter split output (fc2)
// EPI 4: qkv + fused RoPE, scatter to g_q/g_k/g_v in (B,H,N,DH) layout
#define SLDA 20

template<int EPI>
__global__ void __launch_bounds__(256, 2) gemm_tf32_kernel(
    const float* __restrict__ A, const float* __restrict__ Bw,
    float* __restrict__ C, int M, int Nc, int K,
    const float* __restrict__ bias, const float* __restrict__ res,
    const float* __restrict__ modv, float* __restrict__ outp,
    const float* __restrict__ rope)
{
    __shared__ __align__(16) float As[2][128][SLDA];
    __shared__ __align__(16) float Bs[2][128][SLDA];

    int tid  = threadIdx.x;
    int lane = tid & 31;
    int warp = tid >> 5;
    int wm = warp >> 2;
    int wn = warp & 3;
    int mBase = blockIdx.y * 128;
    int nBase = blockIdx.x * 128;

    int lrow = tid >> 2;         // 0..63
    int lq   = tid & 3;

    const float* Ap = A  + (size_t)(mBase + lrow) * K + lq * 4;
    const float* Bp = Bw + (size_t)(nBase + lrow) * K + lq * 4;

    uint32_t sA = (uint32_t)__cvta_generic_to_shared(&As[0][0][0]);
    uint32_t sB = (uint32_t)__cvta_generic_to_shared(&Bs[0][0][0]);
    uint32_t dA0 = sA + ((uint32_t)lrow * SLDA + lq * 4) * 4;
    uint32_t dA1 = sA + ((uint32_t)(lrow + 64) * SLDA + lq * 4) * 4;
    uint32_t dB0 = sB + ((uint32_t)lrow * SLDA + lq * 4) * 4;
    uint32_t dB1 = sB + ((uint32_t)(lrow + 64) * SLDA + lq * 4) * 4;
    const uint32_t bufStep = 128 * SLDA * 4;

    float acc[4][4][4];
    #pragma unroll
    for (int i = 0; i < 4; ++i)
        #pragma unroll
        for (int j = 0; j < 4; ++j)
            #pragma unroll
            for (int r = 0; r < 4; ++r) acc[i][j][r] = 0.f;

    int nkt = K >> 4;

    cp16(dA0, Ap);               cp16(dA1, Ap + 64 * (size_t)K);
    cp16(dB0, Bp);               cp16(dB1, Bp + 64 * (size_t)K);
    cp_commit();
    cp16(dA0 + bufStep, Ap + 16);               cp16(dA1 + bufStep, Ap + 16 + 64 * (size_t)K);
    cp16(dB0 + bufStep, Bp + 16);               cp16(dB1 + bufStep, Bp + 16 + 64 * (size_t)K);
    cp_commit();

    for (int kt = 0; kt < nkt; ++kt) {
        int buf = kt & 1;
        cp_wait1();
        __syncthreads();

        #pragma unroll
        for (int ks = 0; ks < 16; ks += 8) {
            float a[4][4], b[4][2];
            int kc = ks + (lane & 3);
            #pragma unroll
            for (int mi = 0; mi < 4; ++mi) {
                int m0 = wm * 64 + mi * 16 + (lane >> 2);
                a[mi][0] = to_tf32(As[buf][m0][kc]);
                a[mi][1] = to_tf32(As[buf][m0 + 8][kc]);
                a[mi][2] = to_tf32(As[buf][m0][kc + 4]);
                a[mi][3] = to_tf32(As[buf][m0 + 8][kc + 4]);
            }
            #pragma unroll
            for (int ni = 0; ni < 4; ++ni) {
                int n0 = wn * 32 + ni * 8 + (lane >> 2);
                b[ni][0] = to_tf32(Bs[buf][n0][kc]);
                b[ni][1] = to_tf32(Bs[buf][n0][kc + 4]);
            }
            #pragma unroll
            for (int mi = 0; mi < 4; ++mi)
                #pragma unroll
                for (int ni = 0; ni < 4; ++ni)
                    mma_tf32(acc[mi][ni], a[mi][0], a[mi][1], a[mi][2], a[mi][3],
                             b[ni][0], b[ni][1]);
        }
        __syncthreads();

        if (kt + 2 < nkt) {
            int off = (kt + 2) * 16;
            uint32_t bofs = buf * bufStep;
            cp16(dA0 + bofs, Ap + off);             cp16(dA1 + bofs, Ap + off + 64 * (size_t)K);
            cp16(dB0 + bofs, Bp + off);             cp16(dB1 + bofs, Bp + off + 64 * (size_t)K);
        }
        cp_commit();
    }

    // ---------------- epilogue ----------------
    int whichQ = 0, hHead = 0;
    if (EPI == 4) {
        whichQ = nBase / DMODEL;
        hHead  = (nBase % DMODEL) >> 7;
    }

    #pragma unroll
    for (int mi = 0; mi < 4; ++mi) {
        int rbase = mBase + wm * 64 + mi * 16 + (lane >> 2);
        #pragma unroll
        for (int half = 0; half < 2; ++half) {
            int row = rbase + half * 8;
            int b_idx = row / NTOK;
            int n_idx = row - b_idx * NTOK;
            #pragma unroll
            for (int ni = 0; ni < 4; ++ni) {
                int col = nBase + wn * 32 + ni * 8 + (lane & 3) * 2;
                float v0 = acc[mi][ni][half * 2 + 0];
                float v1 = acc[mi][ni][half * 2 + 1];
                if (EPI == 1) {
                    v0 = gelu_tanh(v0 + bias[col]);
                    v1 = gelu_tanh(v1 + bias[col + 1]);
                } else if (EPI == 2) {
                    float g0 = modv[b_idx * TD + 2 * DMODEL + col];
                    float g1 = modv[b_idx * TD + 2 * DMODEL + col + 1];
                    v0 = res[(size_t)row * Nc + col]     + g0 * v0;
                    v1 = res[(size_t)row * Nc + col + 1] + g1 * v1;
                } else if (EPI == 3) {
                    v0 = v0 + bias[col]     + res[(size_t)row * Nc + col];
                    v1 = v1 + bias[col + 1] + res[(size_t)row * Nc + col + 1];
                }
                if (EPI == 4) {
                    int d = col & 127;
                    size_t o = ((size_t)(b_idx * NH + hHead) * NTOK + n_idx) * DHEAD + d;
                    if (whichQ == 2) {
                        *(float2*)&g_v[o] = make_float2(v0, v1);
                    } else {
                        float cs = 0.f, sn = 0.f;
                        if (n_idx >= LTXT) {
                            float2 rp = *(const float2*)&rope[
                                (size_t)(b_idx * NIMG + n_idx - LTXT) * DHEAD + d];
                            cs = rp.x; sn = rp.y;
                        }
                        float2 qo = make_float2(v0 * cs - v1 * sn, v1 * cs + v0 * sn);
                        if (whichQ == 0) *(float2*)&g_q[o] = qo;
                        else             *(float2*)&g_k[o] = qo;
                    }
                } else if (EPI == 3) {
                    float* dst = (n_idx < LTXT)
                        ? outp + ((size_t)(b_idx * LTXT + n_idx) * DMODEL + col)
                        : outp + ((size_t)(BATCH * LTXT * DMODEL)
                                  + (size_t)(b_idx * NIMG + n_idx - LTXT) * DMODEL + col);
                    *(float2*)dst = make_float2(v0, v1);
                } else {
                    *(float2*)&C[(size_t)row * Nc + col] = make_float2(v0, v1);
                }
            }
        }
    }
}

// ---------------- K5: flash attention, 64x64 tiles, 2 CTAs/SM ------------------
// 256 threads, 8 warps in 2x4: wr = 32-q-row block, wc = 16-kv-col block (S) /
// 32-dh block (PV).  P tile ALIASES the K tile (K fully consumed by S-mma before
// P store; extra barrier makes the overwrite safe).  Smem = 103 KB -> 2 CTAs/SM
// so the two CTAs' softmax/load phases overlap each other's tensor phases.
#define AQ   64
#define AKV  64
#define QSTR 132
#define KSTR 132
#define VSTR 68
#define PSTR 68
#define ATH  256
#define ATT_SMEM_FLOATS (AQ*QSTR + AKV*KSTR + DHEAD*VSTR + 3*AQ)
#define ATT_SMEM_BYTES  (ATT_SMEM_FLOATS * 4)

__global__ void __launch_bounds__(ATH) attn_kernel()
{
    extern __shared__ float sm[];
    float* Qs   = sm;                       // [64][132]
    float* KP   = Qs + AQ * QSTR;           // [64][132] as K  /  [64][68] as P
    float* Vt   = KP + AKV * KSTR;          // [128][68]  (dh-major, transposed V)
    float* rowm = Vt + DHEAD * VSTR;
    float* rowl = rowm + AQ;
    float* rowc = rowl + AQ;

    int tid  = threadIdx.x;
    int lane = tid & 31;
    int warp = tid >> 5;                    // 0..7
    int wr = warp & 1;                      // q-row block (32 rows)
    int wc = warp >> 1;                     // 0..3
    int bh  = blockIdx.y;
    int b   = bh / NH;
    int h   = bh - b * NH;
    int q0  = blockIdx.x * AQ;

    const float* Qg = g_q + ((size_t)bh * NTOK + q0) * DHEAD;
    const float* Kg = g_k + (size_t)bh * NTOK * DHEAD;
    const float* Vg = g_v + (size_t)bh * NTOK * DHEAD;

    // Q: 64 rows x 32 float4 = 2048 / 256 = 8 iters
    #pragma unroll
    for (int it = 0; it < 8; ++it) {
        int f = it * ATH + tid;
        int n = f >> 5;
        int k4 = (f & 31) * 4;
        float4 v = *(const float4*)&Qg[(size_t)n * DHEAD + k4];
        v.x = to_tf32(v.x); v.y = to_tf32(v.y); v.z = to_tf32(v.z); v.w = to_tf32(v.w);
        *(float4*)&Qs[n * QSTR + k4] = v;
    }
    if (tid < AQ) { rowm[tid] = -1e30f; rowl[tid] = 0.f; }

    float accO[2][4][4];
    #pragma unroll
    for (int mi = 0; mi < 2; ++mi)
        #pragma unroll
        for (int ni = 0; ni < 4; ++ni)
            #pragma unroll
            for (int r = 0; r < 4; ++r) accO[mi][ni][r] = 0.f;

    __syncthreads();

    const float scale = 0.08838834764831845f;   // DH^-0.5
    int rows0 = wr * 32;
    int qrow  = lane >> 2;                      // 0..7

    for (int t = 0; t < NTOK / AKV; ++t) {
        // K: 2048 float4 / 256 = 8 iters
        #pragma unroll
        for (int it = 0; it < 8; ++it) {
            int f = it * ATH + tid;
            int n = f >> 5;
            int k4 = (f & 31) * 4;
            float4 v = *(const float4*)&Kg[((size_t)t * AKV + n) * DHEAD + k4];
            v.x = to_tf32(v.x); v.y = to_tf32(v.y); v.z = to_tf32(v.z); v.w = to_tf32(v.w);
            *(float4*)&KP[n * KSTR + k4] = v;
        }
        // V transposed: 2048 float4 / 256 = 8 iters
        #pragma unroll
        for (int it = 0; it < 8; ++it) {
            int f = it * ATH + tid;
            int kq = f >> 6;                // 0..31
            int n  = f & 63;
            float4 v = *(const float4*)&Vg[((size_t)t * AKV + n) * DHEAD + kq * 4];
            Vt[(kq * 4 + 0) * VSTR + n] = to_tf32(v.x);
            Vt[(kq * 4 + 1) * VSTR + n] = to_tf32(v.y);
            Vt[(kq * 4 + 2) * VSTR + n] = to_tf32(v.z);
            Vt[(kq * 4 + 3) * VSTR + n] = to_tf32(v.w);
        }
        __syncthreads();

        // ---- S = Q K^T (warp tile 32x16) ----
        float accS[2][2][4];
        #pragma unroll
        for (int mi = 0; mi < 2; ++mi)
            #pragma unroll
            for (int ni = 0; ni < 2; ++ni)
                #pragma unroll
                for (int r = 0; r < 4; ++r) accS[mi][ni][r] = 0.f;

        #pragma unroll
        for (int k8 = 0; k8 < DHEAD / 8; ++k8) {
            int kc = k8 * 8 + (lane & 3);
            float a[2][4], bb[2][2];
            #pragma unroll
            for (int mi = 0; mi < 2; ++mi) {
                int r = rows0 + mi * 16 + qrow;
                a[mi][0] = Qs[r * QSTR + kc];
                a[mi][1] = Qs[(r + 8) * QSTR + kc];
                a[mi][2] = Qs[r * QSTR + kc + 4];
                a[mi][3] = Qs[(r + 8) * QSTR + kc + 4];
            }
            #pragma unroll
            for (int ni = 0; ni < 2; ++ni) {
                int n0 = wc * 16 + ni * 8 + qrow;
                bb[ni][0] = KP[n0 * KSTR + kc];
                bb[ni][1] = KP[n0 * KSTR + kc + 4];
            }
            #pragma unroll
            for (int mi = 0; mi < 2; ++mi)
                #pragma unroll
                for (int ni = 0; ni < 2; ++ni)
                    mma_tf32(accS[mi][ni], a[mi][0], a[mi][1], a[mi][2], a[mi][3],
                             bb[ni][0], bb[ni][1]);
        }
        __syncthreads();     // ALL warps done reading K before P overwrites it

        // store scaled S into the aliased P tile
        #pragma unroll
        for (int mi = 0; mi < 2; ++mi) {
            #pragma unroll
            for (int ni = 0; ni < 2; ++ni) {
                int col = wc * 16 + ni * 8 + 2 * (lane & 3);
                int r0 = rows0 + mi * 16 + qrow;
                *(float2*)&KP[r0 * PSTR + col] =
                    make_float2(accS[mi][ni][0] * scale, accS[mi][ni][1] * scale);
                *(float2*)&KP[(r0 + 8) * PSTR + col] =
                    make_float2(accS[mi][ni][2] * scale, accS[mi][ni][3] * scale);
            }
        }
        __syncthreads();

        // ---- online softmax: 4 threads per q-row (quad-strided cols + shfl) ----
        {
            int r4 = tid >> 2;              // 0..63
            int q4 = tid & 3;
            float m_old = rowm[r4];
            float mx = m_old;
            #pragma unroll
            for (int j = 0; j < 16; ++j)
                mx = fmaxf(mx, KP[r4 * PSTR + j * 4 + q4]);
            mx = fmaxf(mx, __shfl_xor_sync(0xffffffffu, mx, 1));
            mx = fmaxf(mx, __shfl_xor_sync(0xffffffffu, mx, 2));
            float l = 0.f;
            #pragma unroll
            for (int j = 0; j < 16; ++j) {
                float p = __expf(KP[r4 * PSTR + j * 4 + q4] - mx);
                KP[r4 * PSTR + j * 4 + q4] = to_tf32(p);
                l += p;
            }
            l += __shfl_xor_sync(0xffffffffu, l, 1);
            l += __shfl_xor_sync(0xffffffffu, l, 2);
            if (q4 == 0) {
                float c = __expf(m_old - mx);
                rowm[r4] = mx;
                rowl[r4] = rowl[r4] * c + l;
                rowc[r4] = c;
            }
        }
        __syncthreads();

        // ---- O = O*c + P @ V (warp tile 32x32 of dh) ----
        float c0 = rowc[rows0 + qrow];
        float c1 = rowc[rows0 + 8 + qrow];
        float c2 = rowc[rows0 + 16 + qrow];
        float c3 = rowc[rows0 + 24 + qrow];
        #pragma unroll
        for (int ni = 0; ni < 4; ++ni) {
            accO[0][ni][0] *= c0; accO[0][ni][1] *= c0;
            accO[0][ni][2] *= c1; accO[0][ni][3] *= c1;
            accO[1][ni][0] *= c2; accO[1][ni][1] *= c2;
            accO[1][ni][2] *= c3; accO[1][ni][3] *= c3;
        }
        #pragma unroll
        for (int k8 = 0; k8 < AKV / 8; ++k8) {
            int kc = k8 * 8 + (lane & 3);
            float a[2][4], bb[4][2];
            #pragma unroll
            for (int mi = 0; mi < 2; ++mi) {
                int r = rows0 + mi * 16 + qrow;
                a[mi][0] = KP[r * PSTR + kc];
                a[mi][1] = KP[(r + 8) * PSTR + kc];
                a[mi][2] = KP[r * PSTR + kc + 4];
                a[mi][3] = KP[(r + 8) * PSTR + kc + 4];
            }
            #pragma unroll
            for (int ni = 0; ni < 4; ++ni) {
                int n0 = wc * 32 + ni * 8 + qrow;   // dh column
                bb[ni][0] = Vt[n0 * VSTR + kc];
                bb[ni][1] = Vt[n0 * VSTR + kc + 4];
            }
            #pragma unroll
            for (int mi = 0; mi < 2; ++mi)
                #pragma unroll
                for (int ni = 0; ni < 4; ++ni)
                    mma_tf32(accO[mi][ni], a[mi][0], a[mi][1], a[mi][2], a[mi][3],
                             bb[ni][0], bb[ni][1]);
        }
        __syncthreads();     // P fully consumed before next tile's K load
    }

    // ---- final: divide by l, write out ----
    float i0 = 1.f / rowl[rows0 + qrow];
    float i1 = 1.f / rowl[rows0 + 8 + qrow];
    float i2 = 1.f / rowl[rows0 + 16 + qrow];
    float i3 = 1.f / rowl[rows0 + 24 + qrow];
    #pragma unroll
    for (int mi = 0; mi < 2; ++mi) {
        int r0 = rows0 + mi * 16 + qrow;
        float ia = (mi == 0) ? i0 : i2;
        float ib = (mi == 0) ? i1 : i3;
        #pragma unroll
        for (int ni = 0; ni < 4; ++ni) {
            int col = h * DHEAD + wc * 32 + ni * 8 + 2 * (lane & 3);
            float* d0 = &g_attn[(size_t)(b * NTOK + q0 + r0) * DMODEL + col];
            float* d1 = &g_attn[(size_t)(b * NTOK + q0 + r0 + 8) * DMODEL + col];
            *(float2*)d0 = make_float2(accO[mi][ni][0] * ia, accO[mi][ni][1] * ia);
            *(float2*)d1 = make_float2(accO[mi][ni][2] * ib, accO[mi][ni][3] * ib);
        }
    }
}

// ---------------- host launcher ----------------
extern "C" void kernel_launch(void* const* d_in, const int* in_sizes, int n_in,
                              void* d_out, int out_size)
{
    const float* txt      = (const float*)d_in[0];
    const float* img      = (const float*)d_in[1];
    const float* vec      = (const float*)d_in[2];
    const float* img_rope = (const float*)d_in[4];
    const float* w_norm1  = (const float*)d_in[5];
    const float* w_mod    = (const float*)d_in[6];
    const float* b_mod    = (const float*)d_in[7];
    const float* w_qkv    = (const float*)d_in[8];
    const float* w_out    = (const float*)d_in[9];
    const float* w_norm2  = (const float*)d_in[10];
    const float* w_fc1    = (const float*)d_in[11];
    const float* b_fc1    = (const float*)d_in[12];
    const float* w_fc2    = (const float*)d_in[13];
    const float* b_fc2    = (const float*)d_in[14];
    float* out = (float*)d_out;

    float *px, *pxn, *pattn, *ph, *pmod;
    cudaGetSymbolAddress((void**)&px,    g_x);
    cudaGetSymbolAddress((void**)&pxn,   g_xn);
    cudaGetSymbolAddress((void**)&pattn, g_attn);
    cudaGetSymbolAddress((void**)&ph,    g_h);
    cudaGetSymbolAddress((void**)&pmod,  g_mod);

    cudaFuncSetAttribute(attn_kernel, cudaFuncAttributeMaxDynamicSharedMemorySize,
                         ATT_SMEM_BYTES);

    // 1. AdaLN modulation vector
    mod_kernel<<<BATCH * TD, 256>>>(vec, w_mod, b_mod);
    // 2. concat + RMSNorm + modulate
    norm_kernel<true><<<ROWS, 256>>>(txt, img, w_norm1);
    // 3. qkv projection + fused RoPE + head transpose
    gemm_tf32_kernel<4><<<dim3(TD / 128, ROWS / 128), 256>>>(
        pxn, w_qkv, nullptr, ROWS, TD, DMODEL, nullptr, nullptr, nullptr, nullptr, img_rope);
    // 4. flash attention (tf32 tensor, 64-row tiles, 2 CTAs/SM)
    attn_kernel<<<dim3(NTOK / AQ, BATCH * NH), ATH, ATT_SMEM_BYTES>>>();
    // 5. out projection + gated residual
    gemm_tf32_kernel<2><<<dim3(DMODEL / 128, ROWS / 128), 256>>>(
        pattn, w_out, px, ROWS, DMODEL, DMODEL, nullptr, px, pmod, nullptr, nullptr);
    // 6. RMSNorm 2
    norm_kernel<false><<<ROWS, 256>>>(nullptr, nullptr, w_norm2);
    // 7. fc1 + gelu
    gemm_tf32_kernel<1><<<dim3(MLPH / 128, ROWS / 128), 256>>>(
        pxn, w_fc1, ph, ROWS, MLPH, DMODEL, b_fc1, nullptr, nullptr, nullptr, nullptr);
    // 8. fc2 + bias + residual, scatter to split output
    gemm_tf32_kernel<3><<<dim3(DMODEL / 128, ROWS / 128), 256>>>(
        ph, w_fc2, nullptr, ROWS, DMODEL, MLPH, b_fc2, px, nullptr, out, nullptr);
}

// round 14
// speedup vs baseline: 1.1413x; 1.1413x over previous
#include <cuda_runtime.h>
#include <cuda_bf16.h>
#include <math.h>
#include <stdint.h>

// ---------------- problem constants ----------------
#define BATCH   2
#define LTXT    256
#define NIMG    2048
#define NTOK    2304          // LTXT + NIMG
#define DMODEL  1536
#define NH      12
#define DHEAD   128
#define TD      4608          // 3*DMODEL
#define MLPH    6144
#define ROWS    (BATCH*NTOK)  // 4608

// ---------------- device scratch (no allocs allowed) ----------------
__device__ __align__(128) float g_x   [ROWS*DMODEL];
__device__ __align__(128) float g_xn  [ROWS*DMODEL];
__device__ __align__(128) float g_q   [ROWS*DMODEL];
__device__ __align__(128) float g_k   [ROWS*DMODEL];
__device__ __align__(128) float g_v   [ROWS*DMODEL];
__device__ __align__(128) float g_attn[ROWS*DMODEL];
__device__ __align__(128) float g_h   [ROWS*MLPH];
__device__ __align__(128) float g_mod [BATCH*TD];

// ---------------- helpers ----------------
__device__ __forceinline__ float blockReduceSum256(float v, float* red) {
    int tid = threadIdx.x;
    red[tid] = v;
    __syncthreads();
    #pragma unroll
    for (int s = 128; s > 0; s >>= 1) {
        if (tid < s) red[tid] += red[tid + s];
        __syncthreads();
    }
    return red[0];
}

__device__ __forceinline__ float gelu_tanh(float x) {
    float x3 = x * x * x;
    return 0.5f * x * (1.f + tanhf(0.7978845608028654f * (x + 0.044715f * x3)));
}

__device__ __forceinline__ float to_tf32(float x) {
    unsigned u;
    asm("cvt.rna.tf32.f32 %0, %1;" : "=r"(u) : "f"(x));
    return __uint_as_float(u);
}

// pack two floats into bf16x2 (lo in [15:0], hi in [31:16])
__device__ __forceinline__ uint32_t bf2(float lo, float hi) {
    uint32_t r;
    asm("cvt.rn.bf16x2.f32 %0, %1, %2;" : "=r"(r) : "f"(hi), "f"(lo));
    return r;
}

__device__ __forceinline__ void mma_tf32(float c[4], float a0, float a1, float a2, float a3,
                                         float b0, float b1) {
    asm volatile(
        "mma.sync.aligned.m16n8k8.row.col.f32.tf32.tf32.f32 "
        "{%0,%1,%2,%3}, {%4,%5,%6,%7}, {%8,%9}, {%0,%1,%2,%3};"
        : "+f"(c[0]), "+f"(c[1]), "+f"(c[2]), "+f"(c[3])
        : "r"(__float_as_uint(a0)), "r"(__float_as_uint(a1)),
          "r"(__float_as_uint(a2)), "r"(__float_as_uint(a3)),
          "r"(__float_as_uint(b0)), "r"(__float_as_uint(b1)));
}

__device__ __forceinline__ void mma_bf16(float c[4], uint32_t a0, uint32_t a1,
                                         uint32_t a2, uint32_t a3,
                                         uint32_t b0, uint32_t b1) {
    asm volatile(
        "mma.sync.aligned.m16n8k16.row.col.f32.bf16.bf16.f32 "
        "{%0,%1,%2,%3}, {%4,%5,%6,%7}, {%8,%9}, {%0,%1,%2,%3};"
        : "+f"(c[0]), "+f"(c[1]), "+f"(c[2]), "+f"(c[3])
        : "r"(a0), "r"(a1), "r"(a2), "r"(a3), "r"(b0), "r"(b1));
}

__device__ __forceinline__ void cp16(uint32_t dst, const void* src) {
    asm volatile("cp.async.cg.shared.global [%0], [%1], 16;\n" :: "r"(dst), "l"(src));
}
__device__ __forceinline__ void cp_commit() {
    asm volatile("cp.async.commit_group;\n" ::: "memory");
}
__device__ __forceinline__ void cp_wait1() {
    asm volatile("cp.async.wait_group 1;\n" ::: "memory");
}

// ---------------- K1: modulation ----------------
__global__ void __launch_bounds__(256) mod_kernel(
    const float* __restrict__ vec, const float* __restrict__ wmod,
    const float* __restrict__ bmod)
{
    __shared__ float red[256];
    int o = blockIdx.x;
    int b = o / TD;
    int j = o - b * TD;
    const float* v = vec + b * DMODEL;
    const float* w = wmod + (size_t)j * DMODEL;
    float s = 0.f;
    for (int i = threadIdx.x; i < DMODEL; i += 256) {
        float x = v[i];
        s += (x / (1.f + __expf(-x))) * w[i];
    }
    s = blockReduceSum256(s, red);
    if (threadIdx.x == 0) g_mod[o] = s + bmod[j];
}

// ---------------- K2: concat + RMSNorm (+ optional AdaLN modulate) ----------------
template<bool MOD1>
__global__ void __launch_bounds__(256) norm_kernel(
    const float* __restrict__ txt, const float* __restrict__ img,
    const float* __restrict__ w)
{
    __shared__ float red[256];
    int r = blockIdx.x;
    int b = r / NTOK;
    int n = r - b * NTOK;
    float* xrow = g_x + (size_t)r * DMODEL;
    const float* src;
    if (MOD1) {
        src = (n < LTXT) ? txt + (size_t)(b * LTXT + n) * DMODEL
                         : img + (size_t)(b * NIMG + n - LTXT) * DMODEL;
    } else {
        src = xrow;
    }
    float ss = 0.f;
    for (int i = threadIdx.x; i < DMODEL; i += 256) {
        float v = src[i];
        if (MOD1) xrow[i] = v;
        ss += v * v;
    }
    ss = blockReduceSum256(ss, red);
    float inv = rsqrtf(ss * (1.f / DMODEL) + 1e-6f);
    float* dst = g_xn + (size_t)r * DMODEL;
    if (MOD1) {
        const float* shift = g_mod + b * TD;
        const float* scale = shift + DMODEL;
        for (int i = threadIdx.x; i < DMODEL; i += 256)
            dst[i] = xrow[i] * inv * w[i] * (1.f + scale[i]) + shift[i];
    } else {
        for (int i = threadIdx.x; i < DMODEL; i += 256)
            dst[i] = src[i] * inv * w[i];
    }
}

// ---------------- K3: tf32 GEMM, 2-stage cp.async double buffer ----------------
#define SLDA 20

template<int EPI>
__global__ void __launch_bounds__(256, 2) gemm_tf32_kernel(
    const float* __restrict__ A, const float* __restrict__ Bw,
    float* __restrict__ C, int M, int Nc, int K,
    const float* __restrict__ bias, const float* __restrict__ res,
    const float* __restrict__ modv, float* __restrict__ outp,
    const float* __restrict__ rope)
{
    __shared__ __align__(16) float As[2][128][SLDA];
    __shared__ __align__(16) float Bs[2][128][SLDA];

    int tid  = threadIdx.x;
    int lane = tid & 31;
    int warp = tid >> 5;
    int wm = warp >> 2;
    int wn = warp & 3;
    int mBase = blockIdx.y * 128;
    int nBase = blockIdx.x * 128;

    int lrow = tid >> 2;
    int lq   = tid & 3;

    const float* Ap = A  + (size_t)(mBase + lrow) * K + lq * 4;
    const float* Bp = Bw + (size_t)(nBase + lrow) * K + lq * 4;

    uint32_t sA = (uint32_t)__cvta_generic_to_shared(&As[0][0][0]);
    uint32_t sB = (uint32_t)__cvta_generic_to_shared(&Bs[0][0][0]);
    uint32_t dA0 = sA + ((uint32_t)lrow * SLDA + lq * 4) * 4;
    uint32_t dA1 = sA + ((uint32_t)(lrow + 64) * SLDA + lq * 4) * 4;
    uint32_t dB0 = sB + ((uint32_t)lrow * SLDA + lq * 4) * 4;
    uint32_t dB1 = sB + ((uint32_t)(lrow + 64) * SLDA + lq * 4) * 4;
    const uint32_t bufStep = 128 * SLDA * 4;

    float acc[4][4][4];
    #pragma unroll
    for (int i = 0; i < 4; ++i)
        #pragma unroll
        for (int j = 0; j < 4; ++j)
            #pragma unroll
            for (int r = 0; r < 4; ++r) acc[i][j][r] = 0.f;

    int nkt = K >> 4;

    cp16(dA0, Ap);               cp16(dA1, Ap + 64 * (size_t)K);
    cp16(dB0, Bp);               cp16(dB1, Bp + 64 * (size_t)K);
    cp_commit();
    cp16(dA0 + bufStep, Ap + 16);               cp16(dA1 + bufStep, Ap + 16 + 64 * (size_t)K);
    cp16(dB0 + bufStep, Bp + 16);               cp16(dB1 + bufStep, Bp + 16 + 64 * (size_t)K);
    cp_commit();

    for (int kt = 0; kt < nkt; ++kt) {
        int buf = kt & 1;
        cp_wait1();
        __syncthreads();

        #pragma unroll
        for (int ks = 0; ks < 16; ks += 8) {
            float a[4][4], b[4][2];
            int kc = ks + (lane & 3);
            #pragma unroll
            for (int mi = 0; mi < 4; ++mi) {
                int m0 = wm * 64 + mi * 16 + (lane >> 2);
                a[mi][0] = to_tf32(As[buf][m0][kc]);
                a[mi][1] = to_tf32(As[buf][m0 + 8][kc]);
                a[mi][2] = to_tf32(As[buf][m0][kc + 4]);
                a[mi][3] = to_tf32(As[buf][m0 + 8][kc + 4]);
            }
            #pragma unroll
            for (int ni = 0; ni < 4; ++ni) {
                int n0 = wn * 32 + ni * 8 + (lane >> 2);
                b[ni][0] = to_tf32(Bs[buf][n0][kc]);
                b[ni][1] = to_tf32(Bs[buf][n0][kc + 4]);
            }
            #pragma unroll
            for (int mi = 0; mi < 4; ++mi)
                #pragma unroll
                for (int ni = 0; ni < 4; ++ni)
                    mma_tf32(acc[mi][ni], a[mi][0], a[mi][1], a[mi][2], a[mi][3],
                             b[ni][0], b[ni][1]);
        }
        __syncthreads();

        if (kt + 2 < nkt) {
            int off = (kt + 2) * 16;
            uint32_t bofs = buf * bufStep;
            cp16(dA0 + bofs, Ap + off);             cp16(dA1 + bofs, Ap + off + 64 * (size_t)K);
            cp16(dB0 + bofs, Bp + off);             cp16(dB1 + bofs, Bp + off + 64 * (size_t)K);
        }
        cp_commit();
    }

    // ---------------- epilogue ----------------
    int whichQ = 0, hHead = 0;
    if (EPI == 4) {
        whichQ = nBase / DMODEL;
        hHead  = (nBase % DMODEL) >> 7;
    }

    #pragma unroll
    for (int mi = 0; mi < 4; ++mi) {
        int rbase = mBase + wm * 64 + mi * 16 + (lane >> 2);
        #pragma unroll
        for (int half = 0; half < 2; ++half) {
            int row = rbase + half * 8;
            int b_idx = row / NTOK;
            int n_idx = row - b_idx * NTOK;
            #pragma unroll
            for (int ni = 0; ni < 4; ++ni) {
                int col = nBase + wn * 32 + ni * 8 + (lane & 3) * 2;
                float v0 = acc[mi][ni][half * 2 + 0];
                float v1 = acc[mi][ni][half * 2 + 1];
                if (EPI == 1) {
                    v0 = gelu_tanh(v0 + bias[col]);
                    v1 = gelu_tanh(v1 + bias[col + 1]);
                } else if (EPI == 2) {
                    float g0 = modv[b_idx * TD + 2 * DMODEL + col];
                    float g1 = modv[b_idx * TD + 2 * DMODEL + col + 1];
                    v0 = res[(size_t)row * Nc + col]     + g0 * v0;
                    v1 = res[(size_t)row * Nc + col + 1] + g1 * v1;
                } else if (EPI == 3) {
                    v0 = v0 + bias[col]     + res[(size_t)row * Nc + col];
                    v1 = v1 + bias[col + 1] + res[(size_t)row * Nc + col + 1];
                }
                if (EPI == 4) {
                    int d = col & 127;
                    size_t o = ((size_t)(b_idx * NH + hHead) * NTOK + n_idx) * DHEAD + d;
                    if (whichQ == 2) {
                        *(float2*)&g_v[o] = make_float2(v0, v1);
                    } else {
                        float cs = 0.f, sn = 0.f;
                        if (n_idx >= LTXT) {
                            float2 rp = *(const float2*)&rope[
                                (size_t)(b_idx * NIMG + n_idx - LTXT) * DHEAD + d];
                            cs = rp.x; sn = rp.y;
                        }
                        float2 qo = make_float2(v0 * cs - v1 * sn, v1 * cs + v0 * sn);
                        if (whichQ == 0) *(float2*)&g_q[o] = qo;
                        else             *(float2*)&g_k[o] = qo;
                    }
                } else if (EPI == 3) {
                    float* dst = (n_idx < LTXT)
                        ? outp + ((size_t)(b_idx * LTXT + n_idx) * DMODEL + col)
                        : outp + ((size_t)(BATCH * LTXT * DMODEL)
                                  + (size_t)(b_idx * NIMG + n_idx - LTXT) * DMODEL + col);
                    *(float2*)dst = make_float2(v0, v1);
                } else {
                    *(float2*)&C[(size_t)row * Nc + col] = make_float2(v0, v1);
                }
            }
        }
    }
}

// ---------------- K5: flash attention, bf16 mma (m16n8k16), fp32 softmax --------
// Tile 128 q x 64 kv, 256 threads / 8 warps: wr = warp&3 (32-row block),
// wc = warp>>2 (32-kv half for S; 64-dh half for PV).
// Q/K/V/P in smem as bf16x2 (u32); S buffer fp32; P ALIASES S (softmax stages
// S into registers, barrier, then writes P).  104.5 KB smem -> 2 CTAs/SM.
#define AQ    128
#define AKV   64
#define QS32  68      // u32 stride (64 data + 4 pad; ≡4 mod 32 -> conflict-free frags)
#define KS32  68
#define VS32  36      // u32 stride (32 data + 4 pad)
#define PS32  36
#define SSTR  68      // fp32 stride for S
#define ATH   256
#define ATT_SMEM_U32 (AQ*QS32 + AKV*KS32 + DHEAD*VS32 + AQ*SSTR + 3*AQ)
#define ATT_SMEM_BYTES (ATT_SMEM_U32 * 4)

__global__ void __launch_bounds__(ATH, 2) attn_kernel()
{
    extern __shared__ uint32_t smu[];
    uint32_t* Q32 = smu;                          // [128][68] bf16x2
    uint32_t* K32 = Q32 + AQ * QS32;              // [64][68]
    uint32_t* V32 = K32 + AKV * KS32;             // [128][36]  Vt[dh][kvpair]
    float*    Sf  = (float*)(V32 + DHEAD * VS32); // [128][68] fp32 S
    uint32_t* P32 = (uint32_t*)Sf;                // [128][36] bf16x2, ALIASES S
    float* rowm = Sf + AQ * SSTR;
    float* rowl = rowm + AQ;
    float* rowc = rowl + AQ;

    int tid  = threadIdx.x;
    int lane = tid & 31;
    int warp = tid >> 5;
    int wr = warp & 3;
    int wc = warp >> 2;
    int bh  = blockIdx.y;
    int b   = bh / NH;
    int h   = bh - b * NH;
    int q0  = blockIdx.x * AQ;

    const float* Qg = g_q + ((size_t)bh * NTOK + q0) * DHEAD;
    const float* Kg = g_k + (size_t)bh * NTOK * DHEAD;
    const float* Vg = g_v + (size_t)bh * NTOK * DHEAD;

    // Q load: 4096 float4 / 256 threads = 16 iters, pack bf16x2
    #pragma unroll
    for (int it = 0; it < 16; ++it) {
        int f = it * ATH + tid;
        int n = f >> 5;
        int k4 = (f & 31) * 4;
        float4 v = *(const float4*)&Qg[(size_t)n * DHEAD + k4];
        *(uint2*)&Q32[n * QS32 + (f & 31) * 2] =
            make_uint2(bf2(v.x, v.y), bf2(v.z, v.w));
    }
    if (tid < AQ) { rowm[tid] = -1e30f; rowl[tid] = 0.f; }

    float accO[2][8][4];
    #pragma unroll
    for (int mi = 0; mi < 2; ++mi)
        #pragma unroll
        for (int ni = 0; ni < 8; ++ni)
            #pragma unroll
            for (int r = 0; r < 4; ++r) accO[mi][ni][r] = 0.f;

    __syncthreads();

    const float scale = 0.08838834764831845f;   // DH^-0.5
    int rows0 = wr * 32;
    int qrow  = lane >> 2;                      // 0..7
    int q2    = lane & 3;                       // 0..3
    int r2 = tid >> 1;                          // softmax row
    int h2 = tid & 1;                           // softmax column half

    for (int t = 0; t < NTOK / AKV; ++t) {
        // K: 2048 float4 / 256 = 8 iters
        #pragma unroll
        for (int it = 0; it < 8; ++it) {
            int f = it * ATH + tid;
            int n = f >> 5;
            int k4 = (f & 31) * 4;
            float4 v = *(const float4*)&Kg[((size_t)t * AKV + n) * DHEAD + k4];
            *(uint2*)&K32[n * KS32 + (f & 31) * 2] =
                make_uint2(bf2(v.x, v.y), bf2(v.z, v.w));
        }
        // V transposed+paired: V32[dh][j] = pack(V[2j][dh], V[2j+1][dh]); 4 iters
        #pragma unroll
        for (int it = 0; it < 4; ++it) {
            int f = it * ATH + tid;             // 0..1023
            int j   = f & 31;                   // kv pair index
            int dh0 = (f >> 5) * 4;             // 4 head dims
            const float* vr0 = &Vg[((size_t)t * AKV + 2 * j)     * DHEAD + dh0];
            const float* vr1 = &Vg[((size_t)t * AKV + 2 * j + 1) * DHEAD + dh0];
            float4 v0 = *(const float4*)vr0;
            float4 v1 = *(const float4*)vr1;
            V32[(dh0 + 0) * VS32 + j] = bf2(v0.x, v1.x);
            V32[(dh0 + 1) * VS32 + j] = bf2(v0.y, v1.y);
            V32[(dh0 + 2) * VS32 + j] = bf2(v0.z, v1.z);
            V32[(dh0 + 3) * VS32 + j] = bf2(v0.w, v1.w);
        }
        __syncthreads();

        // ---- S = Q K^T : warp tile 32 x 32, 8 k16 steps ----
        float accS[2][4][4];
        #pragma unroll
        for (int mi = 0; mi < 2; ++mi)
            #pragma unroll
            for (int ni = 0; ni < 4; ++ni)
                #pragma unroll
                for (int r = 0; r < 4; ++r) accS[mi][ni][r] = 0.f;

        #pragma unroll
        for (int ks = 0; ks < 8; ++ks) {
            int kb = ks * 8;
            uint32_t a[2][4], bb[4][2];
            #pragma unroll
            for (int mi = 0; mi < 2; ++mi) {
                int r = rows0 + mi * 16 + qrow;
                a[mi][0] = Q32[r * QS32 + kb + q2];
                a[mi][1] = Q32[(r + 8) * QS32 + kb + q2];
                a[mi][2] = Q32[r * QS32 + kb + 4 + q2];
                a[mi][3] = Q32[(r + 8) * QS32 + kb + 4 + q2];
            }
            #pragma unroll
            for (int ni = 0; ni < 4; ++ni) {
                int n0 = wc * 32 + ni * 8 + qrow;
                bb[ni][0] = K32[n0 * KS32 + kb + q2];
                bb[ni][1] = K32[n0 * KS32 + kb + 4 + q2];
            }
            #pragma unroll
            for (int mi = 0; mi < 2; ++mi)
                #pragma unroll
                for (int ni = 0; ni < 4; ++ni)
                    mma_bf16(accS[mi][ni], a[mi][0], a[mi][1], a[mi][2], a[mi][3],
                             bb[ni][0], bb[ni][1]);
        }
        // store scaled S (fp32) — previous tile's P (aliased) already consumed
        #pragma unroll
        for (int mi = 0; mi < 2; ++mi) {
            #pragma unroll
            for (int ni = 0; ni < 4; ++ni) {
                int col = wc * 32 + ni * 8 + 2 * q2;
                int r0 = rows0 + mi * 16 + qrow;
                *(float2*)&Sf[r0 * SSTR + col] =
                    make_float2(accS[mi][ni][0] * scale, accS[mi][ni][1] * scale);
                *(float2*)&Sf[(r0 + 8) * SSTR + col] =
                    make_float2(accS[mi][ni][2] * scale, accS[mi][ni][3] * scale);
            }
        }
        __syncthreads();

        // ---- softmax: 2 threads/row, 32 consecutive cols each ----
        // Phase A: stage S into registers (required before P overwrites S region)
        float s[32];
        #pragma unroll
        for (int i = 0; i < 8; ++i)
            *(float4*)&s[4 * i] = *(const float4*)&Sf[r2 * SSTR + h2 * 32 + 4 * i];
        float m_old = rowm[r2];
        float mx = m_old;
        #pragma unroll
        for (int i = 0; i < 32; ++i) mx = fmaxf(mx, s[i]);
        mx = fmaxf(mx, __shfl_xor_sync(0xffffffffu, mx, 1));
        __syncthreads();          // all S reads staged; safe to overwrite with P

        // Phase B: exp + pack bf16 P + partial l
        float l = 0.f;
        #pragma unroll
        for (int j = 0; j < 16; ++j) {
            float e0 = __expf(s[2 * j]     - mx);
            float e1 = __expf(s[2 * j + 1] - mx);
            l += e0 + e1;
            P32[r2 * PS32 + h2 * 16 + j] = bf2(e0, e1);
        }
        l += __shfl_xor_sync(0xffffffffu, l, 1);
        if (h2 == 0) {
            float c = __expf(m_old - mx);
            rowm[r2] = mx;
            rowl[r2] = rowl[r2] * c + l;
            rowc[r2] = c;
        }
        __syncthreads();

        // ---- O = O*c + P @ V : warp tile 32 x 64(dh), 4 k16 steps ----
        float c0 = rowc[rows0 + qrow];
        float c1 = rowc[rows0 + 8 + qrow];
        float c2 = rowc[rows0 + 16 + qrow];
        float c3 = rowc[rows0 + 24 + qrow];
        #pragma unroll
        for (int ni = 0; ni < 8; ++ni) {
            accO[0][ni][0] *= c0; accO[0][ni][1] *= c0;
            accO[0][ni][2] *= c1; accO[0][ni][3] *= c1;
            accO[1][ni][0] *= c2; accO[1][ni][1] *= c2;
            accO[1][ni][2] *= c3; accO[1][ni][3] *= c3;
        }
        #pragma unroll
        for (int ks = 0; ks < 4; ++ks) {
            int kb = ks * 8;
            uint32_t a[2][4], bb[8][2];
            #pragma unroll
            for (int mi = 0; mi < 2; ++mi) {
                int r = rows0 + mi * 16 + qrow;
                a[mi][0] = P32[r * PS32 + kb + q2];
                a[mi][1] = P32[(r + 8) * PS32 + kb + q2];
                a[mi][2] = P32[r * PS32 + kb + 4 + q2];
                a[mi][3] = P32[(r + 8) * PS32 + kb + 4 + q2];
            }
            #pragma unroll
            for (int ni = 0; ni < 8; ++ni) {
                int n0 = wc * 64 + ni * 8 + qrow;   // dh column
                bb[ni][0] = V32[n0 * VS32 + kb + q2];
                bb[ni][1] = V32[n0 * VS32 + kb + 4 + q2];
            }
            #pragma unroll
            for (int mi = 0; mi < 2; ++mi)
                #pragma unroll
                for (int ni = 0; ni < 8; ++ni)
                    mma_bf16(accO[mi][ni], a[mi][0], a[mi][1], a[mi][2], a[mi][3],
                             bb[ni][0], bb[ni][1]);
        }
        __syncthreads();          // P/Vt/K fully consumed before next tile loads
    }

    // ---- final: divide by l, write out ----
    float i0 = 1.f / rowl[rows0 + qrow];
    float i1 = 1.f / rowl[rows0 + 8 + qrow];
    float i2 = 1.f / rowl[rows0 + 16 + qrow];
    float i3 = 1.f / rowl[rows0 + 24 + qrow];
    #pragma unroll
    for (int mi = 0; mi < 2; ++mi) {
        int r0 = rows0 + mi * 16 + qrow;
        float ia = (mi == 0) ? i0 : i2;
        float ib = (mi == 0) ? i1 : i3;
        #pragma unroll
        for (int ni = 0; ni < 8; ++ni) {
            int col = h * DHEAD + wc * 64 + ni * 8 + 2 * q2;
            float* d0 = &g_attn[(size_t)(b * NTOK + q0 + r0) * DMODEL + col];
            float* d1 = &g_attn[(size_t)(b * NTOK + q0 + r0 + 8) * DMODEL + col];
            *(float2*)d0 = make_float2(accO[mi][ni][0] * ia, accO[mi][ni][1] * ia);
            *(float2*)d1 = make_float2(accO[mi][ni][2] * ib, accO[mi][ni][3] * ib);
        }
    }
}

// ---------------- host launcher ----------------
extern "C" void kernel_launch(void* const* d_in, const int* in_sizes, int n_in,
                              void* d_out, int out_size)
{
    const float* txt      = (const float*)d_in[0];
    const float* img      = (const float*)d_in[1];
    const float* vec      = (const float*)d_in[2];
    const float* img_rope = (const float*)d_in[4];
    const float* w_norm1  = (const float*)d_in[5];
    const float* w_mod    = (const float*)d_in[6];
    const float* b_mod    = (const float*)d_in[7];
    const float* w_qkv    = (const float*)d_in[8];
    const float* w_out    = (const float*)d_in[9];
    const float* w_norm2  = (const float*)d_in[10];
    const float* w_fc1    = (const float*)d_in[11];
    const float* b_fc1    = (const float*)d_in[12];
    const float* w_fc2    = (const float*)d_in[13];
    const float* b_fc2    = (const float*)d_in[14];
    float* out = (float*)d_out;

    float *px, *pxn, *pattn, *ph, *pmod;
    cudaGetSymbolAddress((void**)&px,    g_x);
    cudaGetSymbolAddress((void**)&pxn,   g_xn);
    cudaGetSymbolAddress((void**)&pattn, g_attn);
    cudaGetSymbolAddress((void**)&ph,    g_h);
    cudaGetSymbolAddress((void**)&pmod,  g_mod);

    cudaFuncSetAttribute(attn_kernel, cudaFuncAttributeMaxDynamicSharedMemorySize,
                         ATT_SMEM_BYTES);

    // 1. AdaLN modulation vector
    mod_kernel<<<BATCH * TD, 256>>>(vec, w_mod, b_mod);
    // 2. concat + RMSNorm + modulate
    norm_kernel<true><<<ROWS, 256>>>(txt, img, w_norm1);
    // 3. qkv projection + fused RoPE + head transpose
    gemm_tf32_kernel<4><<<dim3(TD / 128, ROWS / 128), 256>>>(
        pxn, w_qkv, nullptr, ROWS, TD, DMODEL, nullptr, nullptr, nullptr, nullptr, img_rope);
    // 4. flash attention (bf16 mma, fp32 softmax, 2 CTAs/SM)
    attn_kernel<<<dim3(NTOK / AQ, BATCH * NH), ATH, ATT_SMEM_BYTES>>>();
    // 5. out projection + gated residual
    gemm_tf32_kernel<2><<<dim3(DMODEL / 128, ROWS / 128), 256>>>(
        pattn, w_out, px, ROWS, DMODEL, DMODEL, nullptr, px, pmod, nullptr, nullptr);
    // 6. RMSNorm 2
    norm_kernel<false><<<ROWS, 256>>>(nullptr, nullptr, w_norm2);
    // 7. fc1 + gelu
    gemm_tf32_kernel<1><<<dim3(MLPH / 128, ROWS / 128), 256>>>(
        pxn, w_fc1, ph, ROWS, MLPH, DMODEL, b_fc1, nullptr, nullptr, nullptr, nullptr);
    // 8. fc2 + bias + residual, scatter to split output
    gemm_tf32_kernel<3><<<dim3(DMODEL / 128, ROWS / 128), 256>>>(
        ph, w_fc2, nullptr, ROWS, DMODEL, MLPH, b_fc2, px, nullptr, out, nullptr);
}